// round 15
// baseline (speedup 1.0000x reference)
#include <cuda_runtime.h>
#include <cuda_fp16.h>
#include <math.h>
#include <stdint.h>

#define BSZ   8
#define TLEN  2048
#define CDIM  1024
#define DDIM  1024
#define MTOT  (BSZ * TLEN)   // 16384

#define SSEG  32
#define LSEG  (TLEN / SSEG)  // 64

// ---------------- scratch (static device globals; no allocs allowed) ----------
__device__ __align__(256) __half g_xk[MTOT * CDIM];
__device__ __align__(256) __half g_xv[MTOT * CDIM];
__device__ __align__(256) __half g_xr[MTOT * CDIM];
__device__ __align__(256) float  g_k [MTOT * DDIM];
__device__ __align__(256) float  g_v [MTOT * DDIM];
__device__ __align__(256) float  g_r [MTOT * DDIM];   // sigmoid(r)
__device__ __align__(256) __half g_rwkv[MTOT * DDIM];
__device__ __align__(256) __half g_Wk[DDIM * CDIM];
__device__ __align__(256) __half g_Wv[DDIM * CDIM];
__device__ __align__(256) __half g_Wr[DDIM * CDIM];
__device__ __align__(256) __half g_Wo[CDIM * DDIM];
__device__ __align__(256) float  g_sA[BSZ * SSEG * DDIM];
__device__ __align__(256) float  g_sB[BSZ * SSEG * DDIM];

// ---------------- helpers ------------------------------------------------------
__device__ __forceinline__ void mma_f16(float c[4], const uint32_t a[4],
                                        uint32_t b0, uint32_t b1) {
    asm volatile(
        "mma.sync.aligned.m16n8k16.row.col.f32.f16.f16.f32 "
        "{%0,%1,%2,%3}, {%4,%5,%6,%7}, {%8,%9}, {%0,%1,%2,%3};"
        : "+f"(c[0]), "+f"(c[1]), "+f"(c[2]), "+f"(c[3])
        : "r"(a[0]), "r"(a[1]), "r"(a[2]), "r"(a[3]), "r"(b0), "r"(b1));
}

__device__ __forceinline__ void cp_async16(uint32_t dst, const void* src) {
    asm volatile("cp.async.cg.shared.global [%0], [%1], 16;" ::"r"(dst), "l"(src));
}

__device__ __forceinline__ void ldsm_x4(uint32_t& r0, uint32_t& r1,
                                        uint32_t& r2, uint32_t& r3, uint32_t addr) {
    asm volatile("ldmatrix.sync.aligned.m8n8.x4.shared.b16 {%0,%1,%2,%3}, [%4];"
                 : "=r"(r0), "=r"(r1), "=r"(r2), "=r"(r3) : "r"(addr));
}

union HalfPack {
    __half2 h[2];
    uint2 u;
};

// ---------------- 0. convert all four weight matrices to fp16 -----------------
__global__ void round_weights(const float* __restrict__ wk, const float* __restrict__ wv,
                              const float* __restrict__ wr, const float* __restrict__ wo)
{
    const int per = (DDIM * CDIM) / 4;
    int i = blockIdx.x * blockDim.x + threadIdx.x;
    int sel = i / per;
    int off = i - sel * per;
    const float* s = (sel == 0) ? wk : (sel == 1) ? wv : (sel == 2) ? wr : wo;
    __half* d = (sel == 0) ? g_Wk : (sel == 1) ? g_Wv : (sel == 2) ? g_Wr : g_Wo;
    float4 v = reinterpret_cast<const float4*>(s)[off];
    HalfPack p;
    p.h[0] = __floats2half2_rn(v.x, v.y);
    p.h[1] = __floats2half2_rn(v.z, v.w);
    reinterpret_cast<uint2*>(d)[off] = p.u;
}

// ---------------- 1. time-shift + mixing (fp16 outputs) -----------------------
__global__ void mix_kernel(const float* __restrict__ x,
                           const float* __restrict__ tmk,
                           const float* __restrict__ tmv,
                           const float* __restrict__ tmr)
{
    int idx = blockIdx.x * blockDim.x + threadIdx.x;
    const int c4cnt = CDIM / 4;
    int c4 = idx % c4cnt;
    int m  = idx / c4cnt;
    int t  = m % TLEN;

    float4 xv4 = reinterpret_cast<const float4*>(x)[idx];
    float4 xx4 = (t > 0) ? reinterpret_cast<const float4*>(x)[idx - c4cnt]
                         : make_float4(0.f, 0.f, 0.f, 0.f);
    float4 mk = reinterpret_cast<const float4*>(tmk)[c4];
    float4 mv = reinterpret_cast<const float4*>(tmv)[c4];
    float4 mr = reinterpret_cast<const float4*>(tmr)[c4];

    HalfPack pk, pv, pr;
    pk.h[0] = __floats2half2_rn(xv4.x * mk.x + xx4.x * (1.f - mk.x),
                                xv4.y * mk.y + xx4.y * (1.f - mk.y));
    pk.h[1] = __floats2half2_rn(xv4.z * mk.z + xx4.z * (1.f - mk.z),
                                xv4.w * mk.w + xx4.w * (1.f - mk.w));
    pv.h[0] = __floats2half2_rn(xv4.x * mv.x + xx4.x * (1.f - mv.x),
                                xv4.y * mv.y + xx4.y * (1.f - mv.y));
    pv.h[1] = __floats2half2_rn(xv4.z * mv.z + xx4.z * (1.f - mv.z),
                                xv4.w * mv.w + xx4.w * (1.f - mv.w));
    pr.h[0] = __floats2half2_rn(xv4.x * mr.x + xx4.x * (1.f - mr.x),
                                xv4.y * mr.y + xx4.y * (1.f - mr.y));
    pr.h[1] = __floats2half2_rn(xv4.z * mr.z + xx4.z * (1.f - mr.z),
                                xv4.w * mr.w + xx4.w * (1.f - mr.w));

    reinterpret_cast<uint2*>(g_xk)[idx] = pk.u;
    reinterpret_cast<uint2*>(g_xv)[idx] = pv.u;
    reinterpret_cast<uint2*>(g_xr)[idx] = pr.u;
}

// ---------------- 2. fp16 tensor-core GEMM:  C[M,N] = A[M,K] * B[N,K]^T -------
// 128x128x64 tile, 512 threads / 16 warps (warp tile 32x32), 3-stage cp.async
// pipeline (96KB smem), 128B-row swizzled smem + ldmatrix.x4 + m16n8k16.
#define KCHUNK 64                // halves of K per stage
#define STAGE_BYTES 32768        // A 128*128B + B 128*128B
#define NSTAGE 3

__device__ __forceinline__ void gemm_f16_core(
    const __half* __restrict__ A, const __half* __restrict__ B,
    float* __restrict__ Cf, __half* __restrict__ Ch,
    int N, int act, int bx, int by, char* smc)
{
    const int tid  = threadIdx.x;
    const int lane = tid & 31;
    const int wid  = tid >> 5;          // 0..15
    const int wm = (wid >> 2) << 5;     // 0,32,64,96
    const int wn = (wid & 3) << 5;      // 0,32,64,96
    const int g  = lane >> 2;
    const int tg = lane & 3;
    const int hi = lane >> 3;           // 0..3
    const int rr = lane & 7;            // 0..7 == (fragment row & 7)

    const int K = 1024;

    // ---- producer: 4 threads/row; each does chunks pc and pc+4 (16B each) ----
    const int prow = tid >> 2;          // 0..127
    const int pc   = tid & 3;           // chunk 0..3 (second is +4)
    const uint32_t pm = (uint32_t)(prow & 7);

    const __half* Ag = A + ((((size_t)by) << 7) + prow) * K + (pc << 3);
    const __half* Bg = B + ((((size_t)bx) << 7) + prow) * K + (pc << 3);

    uint32_t sbase = (uint32_t)__cvta_generic_to_shared(smc);
    uint32_t dA0 = sbase + (uint32_t)(prow << 7) + ((((uint32_t)pc) ^ pm) << 4);
    uint32_t dA1 = sbase + (uint32_t)(prow << 7) + ((((uint32_t)pc + 4u) ^ pm) << 4);
    uint32_t dB0 = dA0 + 16384u;
    uint32_t dB1 = dA1 + 16384u;

    // ---- ldmatrix per-lane bases (row&7 == rr for every fragment row) ----
    const uint32_t aRow0 = (uint32_t)(wm + ((hi & 1) << 3) + rr);  // + mi*16
    const uint32_t aHi   = (uint32_t)(hi >> 1);                    // +1 chunk
    const uint32_t bRow0 = (uint32_t)(wn + ((hi >> 1) << 3) + rr); // + nj*16
    const uint32_t bHi   = (uint32_t)(hi & 1);

    float acc[2][4][4];
    #pragma unroll
    for (int i = 0; i < 2; i++)
        #pragma unroll
        for (int j = 0; j < 4; j++)
            #pragma unroll
            for (int l = 0; l < 4; l++) acc[i][j][l] = 0.f;

    const int kIters = K / KCHUNK;      // 16

#define ISSUE2(IT, S)                                                          \
    {                                                                          \
        uint32_t offS = (uint32_t)((S) * STAGE_BYTES);                         \
        const __half* ap = Ag + (size_t)(IT) * KCHUNK;                         \
        const __half* bp = Bg + (size_t)(IT) * KCHUNK;                         \
        cp_async16(dA0 + offS, ap);                                            \
        cp_async16(dA1 + offS, ap + 32);                                       \
        cp_async16(dB0 + offS, bp);                                            \
        cp_async16(dB1 + offS, bp + 32);                                       \
        asm volatile("cp.async.commit_group;" ::);                             \
    }

    ISSUE2(0, 0);
    ISSUE2(1, 1);

    int stage = 0;
    for (int it = 0; it < kIters; ++it) {
        if (it + 1 < kIters) asm volatile("cp.async.wait_group 1;" ::);
        else                 asm volatile("cp.async.wait_group 0;" ::);
        __syncthreads();

        if (it + 2 < kIters) {
            int s2 = it + 2; int st = s2 - (s2 / NSTAGE) * NSTAGE;
            ISSUE2(s2, st);
        }

        uint32_t sA = sbase + (uint32_t)(stage * STAGE_BYTES);
        uint32_t sB = sA + 16384u;

        #pragma unroll
        for (int kq = 0; kq < 4; kq++) {
            const uint32_t kq2 = (uint32_t)(kq << 1);
            uint32_t af[2][4];
            #pragma unroll
            for (int mi = 0; mi < 2; mi++) {
                uint32_t addr = sA + ((aRow0 + (uint32_t)(mi << 4)) << 7) +
                                (((kq2 + aHi) ^ (uint32_t)rr) << 4);
                ldsm_x4(af[mi][0], af[mi][1], af[mi][2], af[mi][3], addr);
            }
            #pragma unroll
            for (int nj = 0; nj < 2; nj++) {
                uint32_t q0, q1, q2, q3;
                uint32_t addr = sB + ((bRow0 + (uint32_t)(nj << 4)) << 7) +
                                (((kq2 + bHi) ^ (uint32_t)rr) << 4);
                ldsm_x4(q0, q1, q2, q3, addr);
                #pragma unroll
                for (int mi = 0; mi < 2; mi++) {
                    mma_f16(acc[mi][nj * 2],     af[mi], q0, q1);
                    mma_f16(acc[mi][nj * 2 + 1], af[mi], q2, q3);
                }
            }
        }
        stage = (stage + 1 == NSTAGE) ? 0 : stage + 1;
    }

    // ---- epilogue ----
    size_t rowBase = (((size_t)by) << 7) + wm + g;
    int colBase = (bx << 7) + wn + (tg << 1);
    #pragma unroll
    for (int mi = 0; mi < 2; mi++) {
        #pragma unroll
        for (int ni = 0; ni < 4; ni++) {
            size_t r0 = rowBase + (mi << 4);
            int col = colBase + (ni << 3);
            float x0 = acc[mi][ni][0], x1 = acc[mi][ni][1];
            float x2 = acc[mi][ni][2], x3 = acc[mi][ni][3];
            if (act) {
                x0 = 1.f / (1.f + expf(-x0));
                x1 = 1.f / (1.f + expf(-x1));
                x2 = 1.f / (1.f + expf(-x2));
                x3 = 1.f / (1.f + expf(-x3));
            }
            if (Ch) {
                *reinterpret_cast<__half2*>(Ch + r0 * N + col)       = __floats2half2_rn(x0, x1);
                *reinterpret_cast<__half2*>(Ch + (r0 + 8) * N + col) = __floats2half2_rn(x2, x3);
            } else {
                *reinterpret_cast<float2*>(Cf + r0 * N + col)       = make_float2(x0, x1);
                *reinterpret_cast<float2*>(Cf + (r0 + 8) * N + col) = make_float2(x2, x3);
            }
        }
    }
}

__global__ __launch_bounds__(512, 2)
void gemm_proj(int dummy)
{
    extern __shared__ char smc[];
    const int z = blockIdx.z;
    const __half* A = (z == 0) ? g_xk : (z == 1) ? g_xv : g_xr;
    const __half* B = (z == 0) ? g_Wk : (z == 1) ? g_Wv : g_Wr;
    float* C        = (z == 0) ? g_k  : (z == 1) ? g_v  : g_r;
    gemm_f16_core(A, B, C, nullptr, DDIM, (z == 2) ? 1 : 0,
                  blockIdx.x, blockIdx.y, smc);
}

__global__ __launch_bounds__(512, 2)
void gemm_out(float* __restrict__ C)
{
    extern __shared__ char smc[];
    gemm_f16_core(g_rwkv, g_Wo, C, nullptr, CDIM, 0, blockIdx.x, blockIdx.y, smc);
}

// ---------------- 3. wkv: segmented parallel scan -----------------------------
#define P1U 8
__global__ __launch_bounds__(256)
void wkv_pass1(const float* __restrict__ time_decay)
{
    int d = blockIdx.x * 256 + threadIdx.x;
    int s = blockIdx.y;
    int b = blockIdx.z;

    float ew = expf(-expf(time_decay[d]));
    const size_t base = ((size_t)b * TLEN + (size_t)s * LSEG) * DDIM + d;
    const float* kp = g_k + base;
    const float* vp = g_v + base;

    float a = 0.f, bb = 0.f;
    for (int t0 = 0; t0 < LSEG; t0 += P1U) {
        float kk[P1U], vv[P1U];
        #pragma unroll
        for (int i = 0; i < P1U; i++) {
            kk[i] = kp[(size_t)(t0 + i) * DDIM];
            vv[i] = vp[(size_t)(t0 + i) * DDIM];
        }
        #pragma unroll
        for (int i = 0; i < P1U; i++) {
            float ek  = expf(kk[i]);
            float ekv = ek * vv[i];
            a  = ew * a  + ekv;
            bb = ew * bb + ek;
        }
    }
    size_t so = ((size_t)b * SSEG + s) * DDIM + d;
    g_sA[so] = a;
    g_sB[so] = bb;
}

__global__ __launch_bounds__(256)
void wkv_scan(const float* __restrict__ time_decay)
{
    int idx = blockIdx.x * 256 + threadIdx.x;   // over BSZ*DDIM
    int b = idx / DDIM;
    int d = idx % DDIM;

    float ewL = expf(-expf(time_decay[d]) * (float)LSEG);   // ew^LSEG exactly
    float a = 0.f, bb = 0.f;
    #pragma unroll 4
    for (int s = 0; s < SSEG; s++) {
        size_t o = ((size_t)b * SSEG + s) * DDIM + d;
        float A = g_sA[o], B = g_sB[o];
        g_sA[o] = a;
        g_sB[o] = bb;
        a  = ewL * a  + A;
        bb = ewL * bb + B;
    }
}

#define P2U 8
__global__ __launch_bounds__(256)
void wkv_pass2(const float* __restrict__ time_decay,
               const float* __restrict__ time_first)
{
    int d = blockIdx.x * 256 + threadIdx.x;
    int s = blockIdx.y;
    int b = blockIdx.z;

    float ew = expf(-expf(time_decay[d]));
    float eu = expf(time_first[d]);

    size_t so = ((size_t)b * SSEG + s) * DDIM + d;
    float a = g_sA[so], bb = g_sB[so];

    const size_t base = ((size_t)b * TLEN + (size_t)s * LSEG) * DDIM + d;
    const float* kp = g_k + base;
    const float* vp = g_v + base;
    const float* rp = g_r + base;
    __half*      op = g_rwkv + base;

    for (int t0 = 0; t0 < LSEG; t0 += P2U) {
        float kk[P2U], vv[P2U], rr[P2U];
        #pragma unroll
        for (int i = 0; i < P2U; i++) {
            kk[i] = kp[(size_t)(t0 + i) * DDIM];
            vv[i] = vp[(size_t)(t0 + i) * DDIM];
            rr[i] = rp[(size_t)(t0 + i) * DDIM];
        }
        #pragma unroll
        for (int i = 0; i < P2U; i++) {
            float ek  = expf(kk[i]);
            float ekv = ek * vv[i];
            float out = (eu * ekv + a) / (eu * ek + bb);
            op[(size_t)(t0 + i) * DDIM] = __float2half(rr[i] * out);
            a  = ew * a  + ekv;
            bb = ew * bb + ek;
        }
    }
}

// ---------------- launch ------------------------------------------------------
extern "C" void kernel_launch(void* const* d_in, const int* in_sizes, int n_in,
                              void* d_out, int out_size)
{
    const float* x    = (const float*)d_in[0];
    const float* td   = (const float*)d_in[1];
    const float* tf   = (const float*)d_in[2];
    const float* tmk  = (const float*)d_in[3];
    const float* tmv  = (const float*)d_in[4];
    const float* tmr  = (const float*)d_in[5];
    const float* Wk   = (const float*)d_in[6];
    const float* Wv   = (const float*)d_in[7];
    const float* Wr   = (const float*)d_in[8];
    const float* Wo   = (const float*)d_in[9];
    float* out = (float*)d_out;

    size_t smem = (size_t)NSTAGE * STAGE_BYTES;   // 96 KB
    cudaFuncSetAttribute(gemm_proj, cudaFuncAttributeMaxDynamicSharedMemorySize,
                         (int)smem);
    cudaFuncSetAttribute(gemm_out, cudaFuncAttributeMaxDynamicSharedMemorySize,
                         (int)smem);

    // 0. convert weights to fp16
    {
        int n4 = 4 * (DDIM * CDIM) / 4;
        round_weights<<<n4 / 256, 256>>>(Wk, Wv, Wr, Wo);
    }

    // 1. mixing
    {
        int n = MTOT * CDIM / 4;
        mix_kernel<<<n / 256, 256>>>(x, tmk, tmv, tmr);
    }

    // 2. K/V/R projections (merged launch)
    {
        dim3 grid(DDIM / 128, MTOT / 128, 3);
        gemm_proj<<<grid, 512, smem>>>(0);
    }

    // 3. wkv segmented scan
    {
        dim3 grid1(DDIM / 256, SSEG, BSZ);
        wkv_pass1<<<grid1, 256>>>(td);
        wkv_scan<<<(BSZ * DDIM) / 256, 256>>>(td);
        wkv_pass2<<<grid1, 256>>>(td, tf);
    }

    // 4. output projection
    {
        dim3 grid(CDIM / 128, MTOT / 128, 1);
        gemm_out<<<grid, 512, smem>>>(out);
    }
}